// round 1
// baseline (speedup 1.0000x reference)
#include <cuda_runtime.h>
#include <math.h>

// Problem constants
#define BATCH 1024
#define WSZ   8192          // WINDOW_SIZE
#define DIN   65            // D_FEAT + 1
#define NA    66            // augmented rows (65 features + bias row from b_coeff)
#define JN    1023          // impulse length (ir_final)
#define IRL   16382         // 2*(WSZ-1)
#define INV_MAXSTEPS (1.0f/2799.0f)

// Scratch (no allocations allowed -> device globals)
__device__ float        g_mean[BATCH];
__device__ float        g_amps[BATCH];
__device__ unsigned int g_max_u;
__device__ float        g_M[JN * NA];     // M^T layout: [j][i]
__device__ float        g_P[NA * WSZ];    // [i][t]

// ---------------------------------------------------------------------------
// Init: zero accumulation buffers + max register
__global__ void k_init() {
    int idx = blockIdx.x * blockDim.x + threadIdx.x;
    if (idx < NA * WSZ) g_P[idx] = 0.0f;
    if (idx < JN * NA)  g_M[idx] = 0.0f;
    if (idx == 0)       g_max_u = 0u;
}

// ---------------------------------------------------------------------------
// Per-row mean = tanh(x@W_mean+b), amps = sigmoid(x@W_amps+b). One warp / row.
__global__ void k_stats(const float* __restrict__ vel, const float* __restrict__ Kin,
                        const float* __restrict__ Wa, const float* __restrict__ ba,
                        const float* __restrict__ Wm, const float* __restrict__ bm,
                        float* __restrict__ out, int out_size) {
    int gw = (blockIdx.x * blockDim.x + threadIdx.x) >> 5;
    int lane = threadIdx.x & 31;
    if (gw >= BATCH) return;
    float sa = 0.0f, sm = 0.0f;
    #pragma unroll
    for (int i = lane; i < 64; i += 32) {
        float x = vel[gw * 64 + i];
        sa += x * Wa[i];
        sm += x * Wm[i];
    }
    if (lane == 0) {
        float xk = Kin[gw] * INV_MAXSTEPS;
        sa += xk * Wa[64];
        sm += xk * Wm[64];
    }
    #pragma unroll
    for (int o = 16; o; o >>= 1) {
        sa += __shfl_down_sync(0xffffffffu, sa, o);
        sm += __shfl_down_sync(0xffffffffu, sm, o);
    }
    if (lane == 0) {
        float m = tanhf(sm + bm[0]);
        float a = 1.0f / (1.0f + expf(-(sa + ba[0])));
        g_mean[gw] = m;
        g_amps[gw] = a;
        // outputs are (out_noise, mean) flattened: mean goes at tail
        if (out_size >= BATCH * WSZ + BATCH)
            out[BATCH * WSZ + gw] = m;
    }
}

// ---------------------------------------------------------------------------
// Global max over (mean[b] + eps[b,t])
__global__ void k_gmax(const float* __restrict__ eps) {
    const int N = BATCH * WSZ;
    float lm = __int_as_float(0xff800000);  // -inf
    int stride = gridDim.x * blockDim.x;
    for (int idx = blockIdx.x * blockDim.x + threadIdx.x; idx < N; idx += stride) {
        float v = g_mean[idx >> 13] + eps[idx];
        lm = fmaxf(lm, v);
    }
    #pragma unroll
    for (int o = 16; o; o >>= 1)
        lm = fmaxf(lm, __shfl_xor_sync(0xffffffffu, lm, o));
    if ((threadIdx.x & 31) == 0) {
        unsigned b = __float_as_uint(lm);
        unsigned enc = (b & 0x80000000u) ? ~b : (b | 0x80000000u);
        atomicMax(&g_max_u, enc);
    }
}

// ---------------------------------------------------------------------------
// M[i][j] = h(j)/16382 * sum_k g_k * Wrow(i,k) * cos(pi * ((k*(j+7681)) mod 16382) / 8191)
// g_0 = g_{8191} = 1, else 2.  Wrow(65,:) = b_coeff.
// Split-K over blockIdx.y, atomicAdd into g_M.
#define K2_KC 64
#define K2_NSPLIT 8
__global__ void k_mmat(const float* __restrict__ Wc, const float* __restrict__ bc) {
    __shared__ float sW[72 * K2_KC];   // rows 66..71 left as garbage, never written out
    int tx = threadIdx.x & 31;
    int iy = threadIdx.x >> 5;        // 0..7
    int j  = blockIdx.x * 32 + tx;    // 0..1023 (j==1023 guarded at write)
    int m  = j + 7681;
    int kb = blockIdx.y * (WSZ / K2_NSPLIT);
    int ke = kb + (WSZ / K2_NSPLIT);

    float acc[9];
    #pragma unroll
    for (int q = 0; q < 9; q++) acc[q] = 0.0f;

    int ph = (int)(((long long)kb * (long long)m) % IRL);

    for (int k0 = k0 = kb; k0 < ke; k0 += K2_KC) {
        for (int idx = threadIdx.x; idx < NA * K2_KC; idx += blockDim.x) {
            int i  = idx >> 6;
            int kk = idx & 63;
            int k  = k0 + kk;
            float gk = (k == 0 || k == WSZ - 1) ? 1.0f : 2.0f;
            float v  = (i < DIN) ? Wc[i * WSZ + k] : bc[k];
            sW[idx] = v * gk;
        }
        __syncthreads();
        #pragma unroll 4
        for (int kk = 0; kk < K2_KC; kk++) {
            int ph2 = (ph >= 8191) ? (ph - IRL) : ph;
            float c = __cosf((float)ph2 * (3.14159265358979323846f / 8191.0f));
            ph += m; if (ph >= IRL) ph -= IRL;
            #pragma unroll
            for (int q = 0; q < 9; q++)
                acc[q] = fmaf(sW[(iy * 9 + q) * K2_KC + kk], c, acc[q]);
        }
        __syncthreads();
    }
    if (j < JN) {
        float h = 0.5f - 0.5f * cospif((float)(j + 2) * (1.0f / 512.0f));
        float scale = h * (1.0f / 16382.0f);
        #pragma unroll
        for (int q = 0; q < 9; q++) {
            int i = iy * 9 + q;
            if (i < NA) atomicAdd(&g_M[j * NA + i], acc[q] * scale);
        }
    }
}

// ---------------------------------------------------------------------------
// P[i][t] = sum_{j=0..1022} M[i][j] * noise0[t + 510 - j]
// noise0[u] = (mean[0] + eps[0,u]) / gmax for u in [0,WSZ), else 0
// t-tile of 128 per block, split over j via blockIdx.y, atomicAdd into g_P.
#define K3_TT 128
#define K3_JSPLIT 4
__global__ void k_conv(const float* __restrict__ eps) {
    __shared__ float sN[1152];        // noise0[t0-512 .. t0+637]
    __shared__ float sM[32 * 72];     // 32 j-rows, padded stride
    int tx = threadIdx.x & 31;
    int iy = threadIdx.x >> 5;
    int t0 = blockIdx.x * K3_TT;
    int jb = blockIdx.y * 256;
    int je = min(jb + 256, JN);

    float mean0 = g_mean[0];
    unsigned enc = g_max_u;
    float gmax = (enc & 0x80000000u) ? __uint_as_float(enc & 0x7fffffffu)
                                     : __uint_as_float(~enc);
    float inv = 1.0f / gmax;
    for (int s = threadIdx.x; s < 1152; s += blockDim.x) {
        int u = t0 - 512 + s;
        sN[s] = (u >= 0 && u < WSZ) ? (mean0 + eps[u]) * inv : 0.0f;
    }

    float acc[4][9];
    #pragma unroll
    for (int d = 0; d < 4; d++)
        #pragma unroll
        for (int q = 0; q < 9; q++) acc[d][q] = 0.0f;

    for (int j0 = jb; j0 < je; j0 += 32) {
        __syncthreads();
        for (int idx = threadIdx.x; idx < 32 * NA; idx += blockDim.x) {
            int jj = idx / NA, i = idx % NA;
            int j = j0 + jj;
            sM[jj * 72 + i] = (j < JN) ? g_M[j * NA + i] : 0.0f;
        }
        __syncthreads();
        #pragma unroll 4
        for (int jj = 0; jj < 32; jj++) {
            int j = j0 + jj;
            float nv[4];
            #pragma unroll
            for (int d = 0; d < 4; d++)
                nv[d] = sN[tx + 32 * d + 1022 - j];
            #pragma unroll
            for (int q = 0; q < 9; q++) {
                float mv = sM[jj * 72 + iy * 9 + q];
                #pragma unroll
                for (int d = 0; d < 4; d++)
                    acc[d][q] = fmaf(mv, nv[d], acc[d][q]);
            }
        }
    }
    #pragma unroll
    for (int q = 0; q < 9; q++) {
        int i = iy * 9 + q;
        if (i < NA) {
            #pragma unroll
            for (int d = 0; d < 4; d++)
                atomicAdd(&g_P[i * WSZ + t0 + tx + 32 * d], acc[d][q]);
        }
    }
}

// ---------------------------------------------------------------------------
// out[b][t] = amps[b] * sum_i x_aug[b][i] * P[i][t]
#define K4_TB 64
#define K4_TT 128
#define K4_KC 33
__global__ void k_out(const float* __restrict__ vel, const float* __restrict__ Kin,
                      float* __restrict__ out) {
    __shared__ float sP[K4_KC * K4_TT];  // 4224
    __shared__ float sX[K4_TB * K4_KC];  // 2112
    __shared__ float sA[K4_TB];
    int tx = threadIdx.x & 31;
    int iy = threadIdx.x >> 5;
    int t0 = blockIdx.x * K4_TT;
    int b0 = blockIdx.y * K4_TB;
    if (threadIdx.x < K4_TB) sA[threadIdx.x] = g_amps[b0 + threadIdx.x];

    float acc[8][4];
    #pragma unroll
    for (int r = 0; r < 8; r++)
        #pragma unroll
        for (int s = 0; s < 4; s++) acc[r][s] = 0.0f;

    for (int kc = 0; kc < NA; kc += K4_KC) {
        __syncthreads();
        for (int idx = threadIdx.x; idx < K4_KC * K4_TT; idx += 256) {
            int i = idx >> 7, tt = idx & 127;
            sP[idx] = g_P[(kc + i) * WSZ + t0 + tt];
        }
        for (int idx = threadIdx.x; idx < K4_TB * K4_KC; idx += 256) {
            int bb = idx / K4_KC, i0 = idx % K4_KC;
            int i = kc + i0, b = b0 + bb;
            float x;
            if (i < 64)       x = vel[b * 64 + i];
            else if (i == 64) x = Kin[b] * INV_MAXSTEPS;
            else              x = 1.0f;
            sX[idx] = x;
        }
        __syncthreads();
        #pragma unroll
        for (int kk = 0; kk < K4_KC; kk++) {
            float pv[4];
            #pragma unroll
            for (int s = 0; s < 4; s++) pv[s] = sP[kk * K4_TT + tx + 32 * s];
            #pragma unroll
            for (int r = 0; r < 8; r++) {
                float xv = sX[(iy + 8 * r) * K4_KC + kk];
                #pragma unroll
                for (int s = 0; s < 4; s++)
                    acc[r][s] = fmaf(xv, pv[s], acc[r][s]);
            }
        }
    }
    #pragma unroll
    for (int r = 0; r < 8; r++) {
        int b = b0 + iy + 8 * r;
        float a = sA[iy + 8 * r];
        #pragma unroll
        for (int s = 0; s < 4; s++)
            out[b * WSZ + t0 + tx + 32 * s] = a * acc[r][s];
    }
}

// ---------------------------------------------------------------------------
extern "C" void kernel_launch(void* const* d_in, const int* in_sizes, int n_in,
                              void* d_out, int out_size) {
    const float* vel = (const float*)d_in[0];  // (1024, 64)
    const float* Kin = (const float*)d_in[1];  // (1024, 1)
    const float* eps = (const float*)d_in[2];  // (1024, 8192)
    const float* Wc  = (const float*)d_in[3];  // (65, 8192)
    const float* bc  = (const float*)d_in[4];  // (8192,)
    const float* Wa  = (const float*)d_in[5];  // (65, 1)
    const float* ba  = (const float*)d_in[6];  // (1,)
    const float* Wm  = (const float*)d_in[7];  // (65, 1)
    const float* bm  = (const float*)d_in[8];  // (1,)
    float* out = (float*)d_out;

    k_init <<< (NA * WSZ + 255) / 256, 256 >>> ();
    k_stats<<< 32, 1024 >>> (vel, Kin, Wa, ba, Wm, bm, out, out_size);
    k_gmax <<< 1024, 256 >>> (eps);
    k_mmat <<< dim3(32, K2_NSPLIT), 256 >>> (Wc, bc);
    k_conv <<< dim3(WSZ / K3_TT, K3_JSPLIT), 256 >>> (eps);
    k_out  <<< dim3(WSZ / K4_TT, BATCH / K4_TB), 256 >>> (vel, Kin, out);
}

// round 2
// speedup vs baseline: 1.3934x; 1.3934x over previous
#include <cuda_runtime.h>
#include <math.h>

// Problem constants
#define BATCH 1024
#define WSZ   8192
#define DIN   65
#define NA    66            // 65 features + bias row
#define JN    1023          // impulse length
#define IRL   16382         // 2*(WSZ-1)
#define MI_N  513           // distinct cosine columns (mirror symmetry)
#define INV_MAXSTEPS (1.0f/2799.0f)
#define PI_OVER_8191 (3.14159265358979323846f/8191.0f)

// Scratch (device globals; no allocations allowed)
__device__ float        g_mean[BATCH];
__device__ float        g_amps[BATCH];
__device__ unsigned int g_max_u;
__device__ float        g_D[MI_N * NA];   // compact windowed DCT columns [mi][i], h folded
__device__ float        g_P[NA * WSZ];    // conv result [i][t]

// ---------------------------------------------------------------------------
__global__ void k_init() {
    int idx = blockIdx.x * blockDim.x + threadIdx.x;
    if (idx < NA * WSZ)  g_P[idx] = 0.0f;
    if (idx < MI_N * NA) g_D[idx] = 0.0f;
    if (idx == 0)        g_max_u = 0u;
}

// ---------------------------------------------------------------------------
__global__ void k_stats(const float* __restrict__ vel, const float* __restrict__ Kin,
                        const float* __restrict__ Wa, const float* __restrict__ ba,
                        const float* __restrict__ Wm, const float* __restrict__ bm,
                        float* __restrict__ out, int out_size) {
    int gw = (blockIdx.x * blockDim.x + threadIdx.x) >> 5;
    int lane = threadIdx.x & 31;
    if (gw >= BATCH) return;
    float sa = 0.0f, sm = 0.0f;
    #pragma unroll
    for (int i = lane; i < 64; i += 32) {
        float x = vel[gw * 64 + i];
        sa += x * Wa[i];
        sm += x * Wm[i];
    }
    if (lane == 0) {
        float xk = Kin[gw] * INV_MAXSTEPS;
        sa += xk * Wa[64];
        sm += xk * Wm[64];
    }
    #pragma unroll
    for (int o = 16; o; o >>= 1) {
        sa += __shfl_down_sync(0xffffffffu, sa, o);
        sm += __shfl_down_sync(0xffffffffu, sm, o);
    }
    if (lane == 0) {
        float m = tanhf(sm + bm[0]);
        float a = 1.0f / (1.0f + expf(-(sa + ba[0])));
        g_mean[gw] = m;
        g_amps[gw] = a;
        if (out_size >= BATCH * WSZ + BATCH)
            out[BATCH * WSZ + gw] = m;
    }
}

// ---------------------------------------------------------------------------
__global__ void k_gmax(const float* __restrict__ eps) {
    const int N = BATCH * WSZ;
    float lm = __int_as_float(0xff800000);
    int stride = gridDim.x * blockDim.x;
    for (int idx = blockIdx.x * blockDim.x + threadIdx.x; idx < N; idx += stride) {
        float v = g_mean[idx >> 13] + eps[idx];
        lm = fmaxf(lm, v);
    }
    #pragma unroll
    for (int o = 16; o; o >>= 1)
        lm = fmaxf(lm, __shfl_xor_sync(0xffffffffu, lm, o));
    if ((threadIdx.x & 31) == 0) {
        unsigned b = __float_as_uint(lm);
        unsigned enc = (b & 0x80000000u) ? ~b : (b | 0x80000000u);
        atomicMax(&g_max_u, enc);
    }
}

// ---------------------------------------------------------------------------
// g_D[mi][i] = h(j(mi))/16382 * sum_k gk * Wrow(i,k) * cos(2*pi*k*(7679+mi)/16382)
//   mi=0 -> j=1022, mi=1 -> j=1021, mi>=2 -> j=mi-2 (== mirrored 1020-(mi-2))
// Block: 288 threads = 9 warps x 8 i-rows (72 >= 66). Each thread: 2 m's x 8 i's.
// Grid (9 m-tiles of 64, 64 k-splits of 128).
#define MM_KCH 128
#define MM_KSPLIT 64
__global__ void __launch_bounds__(288) k_mmat(const float* __restrict__ Wc,
                                              const float* __restrict__ bc) {
    __shared__ float sW[64 * 72];
    int tx = threadIdx.x & 31;
    int iy = threadIdx.x >> 5;          // 0..8
    int mi0 = blockIdx.x * 64;
    int k0  = blockIdx.y * MM_KCH;

    int mi_[2], mm_[2], ph_[2];
    #pragma unroll
    for (int r = 0; r < 2; r++) {
        mi_[r] = mi0 + tx + 32 * r;
        mm_[r] = 7679 + mi_[r];
        ph_[r] = (int)(((long long)k0 * (long long)mm_[r]) % IRL);
    }

    float acc[8][2];
    #pragma unroll
    for (int q = 0; q < 8; q++) { acc[q][0] = 0.0f; acc[q][1] = 0.0f; }

    for (int kc = 0; kc < MM_KCH; kc += 64) {
        __syncthreads();
        for (int idx = threadIdx.x; idx < 64 * 72; idx += 288) {
            int kk = idx / 72, i = idx % 72;
            int k = k0 + kc + kk;
            float v = (i < DIN) ? Wc[i * WSZ + k] : (i == DIN ? bc[k] : 0.0f);
            float gk = (k == 0 || k == WSZ - 1) ? 1.0f : 2.0f;
            sW[idx] = v * gk;
        }
        __syncthreads();
        #pragma unroll 4
        for (int kk = 0; kk < 64; kk++) {
            float c[2];
            #pragma unroll
            for (int r = 0; r < 2; r++) {
                int p2 = ph_[r] - ((ph_[r] >= 8191) ? IRL : 0);
                c[r] = __cosf((float)p2 * PI_OVER_8191);
                ph_[r] += mm_[r];
                if (ph_[r] >= IRL) ph_[r] -= IRL;
            }
            const float* w = &sW[kk * 72 + iy * 8];
            float4 wa = *reinterpret_cast<const float4*>(w);
            float4 wb = *reinterpret_cast<const float4*>(w + 4);
            float wv[8] = {wa.x, wa.y, wa.z, wa.w, wb.x, wb.y, wb.z, wb.w};
            #pragma unroll
            for (int q = 0; q < 8; q++) {
                acc[q][0] = fmaf(wv[q], c[0], acc[q][0]);
                acc[q][1] = fmaf(wv[q], c[1], acc[q][1]);
            }
        }
    }

    #pragma unroll
    for (int r = 0; r < 2; r++) {
        if (mi_[r] < MI_N) {
            int jh = (mi_[r] >= 2) ? (mi_[r] - 2) : (1022 - mi_[r]);
            float h = 0.5f - 0.5f * cospif((float)(jh + 2) * (1.0f / 512.0f));
            float sc = h * (1.0f / 16382.0f);
            #pragma unroll
            for (int q = 0; q < 8; q++) {
                int i = iy * 8 + q;
                if (i < NA)
                    atomicAdd(&g_D[mi_[r] * NA + i], acc[q][r] * sc);
            }
        }
    }
}

// ---------------------------------------------------------------------------
// Folded symmetric FIR:
// P[i][t] = D[512][i]*n0[t] + sum_{d=1..510} D[512-d][i]*(n0[t+d]+n0[t-d])
//           + D[1][i]*n0[t-511] + D[0][i]*n0[t-512]
#define K3_DSPLIT 8
__global__ void __launch_bounds__(288) k_conv(const float* __restrict__ eps) {
    __shared__ float sN[1152];
    __shared__ float sM[32 * 72];
    int tx = threadIdx.x & 31;
    int iy = threadIdx.x >> 5;          // 0..8
    int t0 = blockIdx.x * 128;
    int y  = blockIdx.y;                // 0..7, d range [1+64y, 64+64y]

    float mean0 = g_mean[0];
    unsigned enc = g_max_u;
    float gmax = (enc & 0x80000000u) ? __uint_as_float(enc & 0x7fffffffu)
                                     : __uint_as_float(~enc);
    float inv = 1.0f / gmax;
    for (int s = threadIdx.x; s < 1152; s += 288) {
        int u = t0 - 512 + s;
        sN[s] = (u >= 0 && u < WSZ) ? (mean0 + eps[u]) * inv : 0.0f;
    }
    __syncthreads();

    float acc[8][4];
    #pragma unroll
    for (int q = 0; q < 8; q++)
        #pragma unroll
        for (int s = 0; s < 4; s++) acc[q][s] = 0.0f;

    if (y == 0) {   // center d=0 and the two tail taps
        #pragma unroll
        for (int q = 0; q < 8; q++) {
            int i = iy * 8 + q;
            if (i < NA) {
                float mC = g_D[512 * NA + i];
                float m1 = g_D[1 * NA + i];
                float m0 = g_D[0 * NA + i];
                #pragma unroll
                for (int s = 0; s < 4; s++) {
                    int x = 512 + tx + 32 * s;
                    acc[q][s] = mC * sN[x] + m1 * sN[x - 511] + m0 * sN[x - 512];
                }
            }
        }
    }

    for (int c = 0; c < 2; c++) {
        int d0 = 1 + 64 * y + 32 * c;
        __syncthreads();
        for (int idx = threadIdx.x; idx < 32 * 72; idx += 288) {
            int dd = idx / 72, i = idx % 72;
            int mi = 512 - (d0 + dd);
            sM[idx] = (i < NA && mi >= 2) ? g_D[mi * NA + i] : 0.0f;
        }
        __syncthreads();
        #pragma unroll 4
        for (int dd = 0; dd < 32; dd++) {
            int d = d0 + dd;
            const float* mrow = &sM[dd * 72 + iy * 8];
            float4 ma = *reinterpret_cast<const float4*>(mrow);
            float4 mb = *reinterpret_cast<const float4*>(mrow + 4);
            float mv[8] = {ma.x, ma.y, ma.z, ma.w, mb.x, mb.y, mb.z, mb.w};
            float f[4];
            #pragma unroll
            for (int s = 0; s < 4; s++) {
                int x = 512 + tx + 32 * s;
                f[s] = sN[x + d] + sN[x - d];
            }
            #pragma unroll
            for (int q = 0; q < 8; q++)
                #pragma unroll
                for (int s = 0; s < 4; s++)
                    acc[q][s] = fmaf(mv[q], f[s], acc[q][s]);
        }
    }

    #pragma unroll
    for (int q = 0; q < 8; q++) {
        int i = iy * 8 + q;
        if (i < NA) {
            #pragma unroll
            for (int s = 0; s < 4; s++)
                atomicAdd(&g_P[i * WSZ + t0 + tx + 32 * s], acc[q][s]);
        }
    }
}

// ---------------------------------------------------------------------------
// out[b][t] = amps[b] * sum_i x_aug[b][i] * P[i][t]
#define K4_TB 64
#define K4_TT 128
#define K4_KC 33
__global__ void k_out(const float* __restrict__ vel, const float* __restrict__ Kin,
                      float* __restrict__ out) {
    __shared__ float sP[K4_KC * K4_TT];
    __shared__ float sX[K4_TB * K4_KC];
    __shared__ float sA[K4_TB];
    int tx = threadIdx.x & 31;
    int iy = threadIdx.x >> 5;
    int t0 = blockIdx.x * K4_TT;
    int b0 = blockIdx.y * K4_TB;
    if (threadIdx.x < K4_TB) sA[threadIdx.x] = g_amps[b0 + threadIdx.x];

    float acc[8][4];
    #pragma unroll
    for (int r = 0; r < 8; r++)
        #pragma unroll
        for (int s = 0; s < 4; s++) acc[r][s] = 0.0f;

    for (int kc = 0; kc < NA; kc += K4_KC) {
        __syncthreads();
        for (int idx = threadIdx.x; idx < K4_KC * K4_TT; idx += 256) {
            int i = idx >> 7, tt = idx & 127;
            sP[idx] = g_P[(kc + i) * WSZ + t0 + tt];
        }
        for (int idx = threadIdx.x; idx < K4_TB * K4_KC; idx += 256) {
            int bb = idx / K4_KC, i0 = idx % K4_KC;
            int i = kc + i0, b = b0 + bb;
            float x;
            if (i < 64)       x = vel[b * 64 + i];
            else if (i == 64) x = Kin[b] * INV_MAXSTEPS;
            else              x = 1.0f;
            sX[idx] = x;
        }
        __syncthreads();
        #pragma unroll
        for (int kk = 0; kk < K4_KC; kk++) {
            float pv[4];
            #pragma unroll
            for (int s = 0; s < 4; s++) pv[s] = sP[kk * K4_TT + tx + 32 * s];
            #pragma unroll
            for (int r = 0; r < 8; r++) {
                float xv = sX[(iy + 8 * r) * K4_KC + kk];
                #pragma unroll
                for (int s = 0; s < 4; s++)
                    acc[r][s] = fmaf(xv, pv[s], acc[r][s]);
            }
        }
    }
    #pragma unroll
    for (int r = 0; r < 8; r++) {
        int b = b0 + iy + 8 * r;
        float a = sA[iy + 8 * r];
        #pragma unroll
        for (int s = 0; s < 4; s++)
            out[b * WSZ + t0 + tx + 32 * s] = a * acc[r][s];
    }
}

// ---------------------------------------------------------------------------
extern "C" void kernel_launch(void* const* d_in, const int* in_sizes, int n_in,
                              void* d_out, int out_size) {
    const float* vel = (const float*)d_in[0];
    const float* Kin = (const float*)d_in[1];
    const float* eps = (const float*)d_in[2];
    const float* Wc  = (const float*)d_in[3];
    const float* bc  = (const float*)d_in[4];
    const float* Wa  = (const float*)d_in[5];
    const float* ba  = (const float*)d_in[6];
    const float* Wm  = (const float*)d_in[7];
    const float* bm  = (const float*)d_in[8];
    float* out = (float*)d_out;

    k_init <<< (NA * WSZ + 255) / 256, 256 >>> ();
    k_stats<<< 32, 1024 >>> (vel, Kin, Wa, ba, Wm, bm, out, out_size);
    k_gmax <<< 1024, 256 >>> (eps);
    k_mmat <<< dim3(9, MM_KSPLIT), 288 >>> (Wc, bc);
    k_conv <<< dim3(WSZ / 128, K3_DSPLIT), 288 >>> (eps);
    k_out  <<< dim3(WSZ / K4_TT, BATCH / K4_TB), 256 >>> (vel, Kin, out);
}

// round 3
// speedup vs baseline: 1.4504x; 1.0409x over previous
#include <cuda_runtime.h>
#include <math.h>

#define BATCH 1024
#define WSZ   8192
#define DIN   65
#define NA    66
#define JN    1023
#define IRL   16382
#define MI_N  513
#define INV_MAXSTEPS (1.0f/2799.0f)
#define PI_OVER_8191 (3.14159265358979323846f/8191.0f)

__device__ float        g_mean[BATCH];
__device__ float        g_amps[BATCH];
__device__ unsigned int g_max_u;
__device__ float        g_D[MI_N * NA];   // windowed DCT columns [mi][i], h folded
__device__ float        g_P[NA * WSZ];    // conv result [i][t]

// ---------------------------------------------------------------------------
__global__ void k_init() {
    int idx = blockIdx.x * blockDim.x + threadIdx.x;
    if (idx < (NA * WSZ) / 4)
        reinterpret_cast<float4*>(g_P)[idx] = make_float4(0.f, 0.f, 0.f, 0.f);
    if (idx < MI_N * NA) g_D[idx] = 0.0f;
    if (idx == 0)        g_max_u = 0u;
}

// ---------------------------------------------------------------------------
// Center column mi=512 (m=8191): cos(2*pi*8191*k/16382) = (-1)^k, h(510)=1.
__global__ void k_center(const float* __restrict__ Wc, const float* __restrict__ bc) {
    __shared__ float red[256];
    int i = blockIdx.x;              // 0..65
    const float* row = (i < DIN) ? &Wc[i * WSZ] : bc;
    float s = 0.0f;
    for (int k = threadIdx.x; k < WSZ; k += 256) {
        float gk = (k == 0 || k == WSZ - 1) ? 1.0f : 2.0f;
        float sgn = (k & 1) ? -1.0f : 1.0f;
        s += row[k] * gk * sgn;
    }
    #pragma unroll
    for (int o = 16; o; o >>= 1) s += __shfl_xor_sync(0xffffffffu, s, o);
    if ((threadIdx.x & 31) == 0) red[threadIdx.x >> 5] = s;
    __syncthreads();
    if (threadIdx.x == 0) {
        float t = 0.0f;
        #pragma unroll
        for (int w = 0; w < 8; w++) t += red[w];
        g_D[512 * NA + i] = t * (1.0f / 16382.0f);
    }
}

// ---------------------------------------------------------------------------
__global__ void k_stats(const float* __restrict__ vel, const float* __restrict__ Kin,
                        const float* __restrict__ Wa, const float* __restrict__ ba,
                        const float* __restrict__ Wm, const float* __restrict__ bm,
                        float* __restrict__ out, int out_size) {
    int gw = (blockIdx.x * blockDim.x + threadIdx.x) >> 5;
    int lane = threadIdx.x & 31;
    if (gw >= BATCH) return;
    float sa = 0.0f, sm = 0.0f;
    #pragma unroll
    for (int i = lane; i < 64; i += 32) {
        float x = vel[gw * 64 + i];
        sa += x * Wa[i];
        sm += x * Wm[i];
    }
    if (lane == 0) {
        float xk = Kin[gw] * INV_MAXSTEPS;
        sa += xk * Wa[64];
        sm += xk * Wm[64];
    }
    #pragma unroll
    for (int o = 16; o; o >>= 1) {
        sa += __shfl_down_sync(0xffffffffu, sa, o);
        sm += __shfl_down_sync(0xffffffffu, sm, o);
    }
    if (lane == 0) {
        float m = tanhf(sm + bm[0]);
        float a = 1.0f / (1.0f + expf(-(sa + ba[0])));
        g_mean[gw] = m;
        g_amps[gw] = a;
        if (out_size >= BATCH * WSZ + BATCH)
            out[BATCH * WSZ + gw] = m;
    }
}

// ---------------------------------------------------------------------------
__global__ void k_gmax(const float* __restrict__ eps) {
    const int N4 = (BATCH * WSZ) / 4;      // 2048 float4 per row
    float lm = __int_as_float(0xff800000);
    int stride = gridDim.x * blockDim.x;
    const float4* e4 = reinterpret_cast<const float4*>(eps);
    for (int idx = blockIdx.x * blockDim.x + threadIdx.x; idx < N4; idx += stride) {
        float m = g_mean[idx >> 11];
        float4 v = e4[idx];
        lm = fmaxf(lm, fmaxf(fmaxf(m + v.x, m + v.y), fmaxf(m + v.z, m + v.w)));
    }
    #pragma unroll
    for (int o = 16; o; o >>= 1)
        lm = fmaxf(lm, __shfl_xor_sync(0xffffffffu, lm, o));
    if ((threadIdx.x & 31) == 0) {
        unsigned b = __float_as_uint(lm);
        unsigned enc = (b & 0x80000000u) ? ~b : (b | 0x80000000u);
        atomicMax(&g_max_u, enc);
    }
}

// ---------------------------------------------------------------------------
// g_D[mi][i] = h(j)/16382 * sum_k gk*Wrow(i,k)*cos(2*pi*k*(7679+mi)/16382), mi<512.
// Shared cosines (computed once per block), smem x smem GEMM.
// Block: 288 thr = 9 warps (iy = i-group of 8). Thread: 4 m (tx*4+r) x 8 i.
// Grid: (4 m-tiles of 128, MM_KSPLIT k-chunks of 128). Sub-chunk 32 k.
#define MM_KSPLIT 64
#define MM_SUB 32
__global__ void __launch_bounds__(288) k_mmat(const float* __restrict__ Wc,
                                              const float* __restrict__ bc) {
    __shared__ float sW[MM_SUB * 76];     // [kk][i], stride 76
    __shared__ float sC[MM_SUB * 128];    // [kk][m]
    int tid = threadIdx.x;
    int tx = tid & 31;
    int iy = tid >> 5;                    // 0..8
    int mi0 = blockIdx.x * 128;
    int k0  = blockIdx.y * 128;

    // cosine-fill state: threads 0..255, m = tid&127, kk parity = tid>>7
    int mfill = tid & 127;
    int half  = (tid >> 7) & 1;
    int mmf = 7679 + mi0 + mfill;
    int ph = 0, step = 0;
    if (tid < 256) {
        ph = (int)(((long long)(k0 + half) * (long long)mmf) % IRL);
        step = 2 * mmf; if (step >= IRL) step -= IRL;
        step += step;   if (step >= IRL) step -= IRL;   // step for kk+=2... 
    }
    // NOTE: step above double-doubled is wrong; recompute cleanly:
    if (tid < 256) { step = 2 * mmf; if (step >= IRL) step -= IRL; }

    float acc[8][4];
    #pragma unroll
    for (int q = 0; q < 8; q++)
        #pragma unroll
        for (int r = 0; r < 4; r++) acc[q][r] = 0.0f;

    for (int c = 0; c < 128 / MM_SUB; c++) {
        int kc = k0 + c * MM_SUB;
        __syncthreads();
        // fill W tile (gk folded)
        for (int idx = tid; idx < 72 * MM_SUB; idx += 288) {
            int i = idx >> 5, kk = idx & 31;
            int k = kc + kk;
            float v = (i < DIN) ? Wc[i * WSZ + k] : (i == DIN ? bc[k] : 0.0f);
            float gk = (k == 0 || k == WSZ - 1) ? 1.0f : 2.0f;
            sW[kk * 76 + i] = v * gk;
        }
        // fill cosines: 16 per thread (kk = half + 2s)
        if (tid < 256) {
            int p = ph;
            #pragma unroll
            for (int s = 0; s < 16; s++) {
                int p2 = p - ((p >= 8191) ? IRL : 0);
                sC[(half + 2 * s) * 128 + mfill] = __cosf((float)p2 * PI_OVER_8191);
                p += step; if (p >= IRL) p -= IRL;
            }
            ph = p;
        }
        __syncthreads();
        #pragma unroll 8
        for (int kk = 0; kk < MM_SUB; kk++) {
            float4 cv = *reinterpret_cast<const float4*>(&sC[kk * 128 + tx * 4]);
            float4 wa = *reinterpret_cast<const float4*>(&sW[kk * 76 + iy * 8]);
            float4 wb = *reinterpret_cast<const float4*>(&sW[kk * 76 + iy * 8 + 4]);
            float wv[8] = {wa.x, wa.y, wa.z, wa.w, wb.x, wb.y, wb.z, wb.w};
            float cr[4] = {cv.x, cv.y, cv.z, cv.w};
            #pragma unroll
            for (int q = 0; q < 8; q++)
                #pragma unroll
                for (int r = 0; r < 4; r++)
                    acc[q][r] = fmaf(wv[q], cr[r], acc[q][r]);
        }
    }

    #pragma unroll
    for (int r = 0; r < 4; r++) {
        int mi = mi0 + tx * 4 + r;           // < 512 always
        int jh = (mi >= 2) ? (mi - 2) : (1022 - mi);
        float h = 0.5f - 0.5f * cospif((float)(jh + 2) * (1.0f / 512.0f));
        float sc = h * (1.0f / 16382.0f);
        #pragma unroll
        for (int q = 0; q < 8; q++) {
            int i = iy * 8 + q;
            if (i < NA)
                atomicAdd(&g_D[mi * NA + i], acc[q][r] * sc);
        }
    }
}

// ---------------------------------------------------------------------------
// Folded symmetric FIR:
// P[i][t] = D[512][i]*n0[t] + sum_{d=1..510} D[512-d][i]*(n0[t+d]+n0[t-d])
//           + D[1][i]*n0[t-511] + D[0][i]*n0[t-512]
// Pair-sums staged in shared once per d-chunk (no per-warp redundancy).
#define K3_DSPLIT 4
__global__ void __launch_bounds__(288) k_conv(const float* __restrict__ eps) {
    __shared__ float sN[1152];
    __shared__ float sM[32 * 76];      // [dd][i]
    __shared__ float sF[32 * 132];     // [dd][t]
    int tid = threadIdx.x;
    int tx = tid & 31;
    int iy = tid >> 5;
    int t0 = blockIdx.x * 128;
    int y  = blockIdx.y;               // d block: [1+128y, 128+128y]

    float mean0 = g_mean[0];
    unsigned enc = g_max_u;
    float gmax = (enc & 0x80000000u) ? __uint_as_float(enc & 0x7fffffffu)
                                     : __uint_as_float(~enc);
    float inv = 1.0f / gmax;
    for (int s = tid; s < 1152; s += 288) {
        int u = t0 - 512 + s;
        sN[s] = (u >= 0 && u < WSZ) ? (mean0 + eps[u]) * inv : 0.0f;
    }
    __syncthreads();

    float acc[8][4];
    #pragma unroll
    for (int q = 0; q < 8; q++)
        #pragma unroll
        for (int s = 0; s < 4; s++) acc[q][s] = 0.0f;

    if (y == 0) {   // center tap + two tail taps
        #pragma unroll
        for (int q = 0; q < 8; q++) {
            int i = iy * 8 + q;
            if (i < NA) {
                float mC = g_D[512 * NA + i];
                float m1 = g_D[1 * NA + i];
                float m0 = g_D[0 * NA + i];
                #pragma unroll
                for (int s = 0; s < 4; s++) {
                    int x = 512 + tx * 4 + s;
                    acc[q][s] = mC * sN[x] + m1 * sN[x - 511] + m0 * sN[x - 512];
                }
            }
        }
    }

    for (int c = 0; c < 4; c++) {
        int d0 = 1 + 128 * y + 32 * c;
        __syncthreads();
        for (int idx = tid; idx < 32 * 72; idx += 288) {
            int dd = idx / 72, i = idx % 72;
            int mi = 512 - (d0 + dd);
            sM[dd * 76 + i] = (i < NA && mi >= 2) ? g_D[mi * NA + i] : 0.0f;
        }
        for (int idx = tid; idx < 32 * 128; idx += 288) {
            int dd = idx >> 7, tt = idx & 127;
            int d = d0 + dd;
            int x = 512 + tt;
            sF[dd * 132 + tt] = sN[x + d] + sN[x - d];
        }
        __syncthreads();
        #pragma unroll 8
        for (int dd = 0; dd < 32; dd++) {
            float4 fv = *reinterpret_cast<const float4*>(&sF[dd * 132 + tx * 4]);
            float4 ma = *reinterpret_cast<const float4*>(&sM[dd * 76 + iy * 8]);
            float4 mb = *reinterpret_cast<const float4*>(&sM[dd * 76 + iy * 8 + 4]);
            float mv[8] = {ma.x, ma.y, ma.z, ma.w, mb.x, mb.y, mb.z, mb.w};
            float fr[4] = {fv.x, fv.y, fv.z, fv.w};
            #pragma unroll
            for (int q = 0; q < 8; q++)
                #pragma unroll
                for (int s = 0; s < 4; s++)
                    acc[q][s] = fmaf(mv[q], fr[s], acc[q][s]);
        }
    }

    #pragma unroll
    for (int q = 0; q < 8; q++) {
        int i = iy * 8 + q;
        if (i < NA) {
            #pragma unroll
            for (int s = 0; s < 4; s++)
                atomicAdd(&g_P[i * WSZ + t0 + tx * 4 + s], acc[q][s]);
        }
    }
}

// ---------------------------------------------------------------------------
// out[b][t] = amps[b] * sum_i x_aug[b][i] * P[i][t]
#define K4_TB 64
#define K4_TT 128
#define K4_KC 33
__global__ void __launch_bounds__(256) k_out(const float* __restrict__ vel,
                                             const float* __restrict__ Kin,
                                             float* __restrict__ out) {
    __shared__ float sP[K4_KC * K4_TT];   // [i][t]
    __shared__ float sX[K4_KC * K4_TB];   // [i][b]
    __shared__ float sA[K4_TB];
    int tid = threadIdx.x;
    int tx = tid & 31;
    int iy = tid >> 5;                     // 0..7
    int t0 = blockIdx.x * K4_TT;
    int b0 = blockIdx.y * K4_TB;
    if (tid < K4_TB) sA[tid] = g_amps[b0 + tid];

    float acc[8][4];
    #pragma unroll
    for (int r = 0; r < 8; r++)
        #pragma unroll
        for (int s = 0; s < 4; s++) acc[r][s] = 0.0f;

    for (int kc = 0; kc < NA; kc += K4_KC) {
        __syncthreads();
        for (int idx = tid; idx < K4_KC * K4_TT; idx += 256) {
            int i = idx >> 7, tt = idx & 127;
            sP[idx] = g_P[(kc + i) * WSZ + t0 + tt];
        }
        for (int idx = tid; idx < K4_KC * K4_TB; idx += 256) {
            int i0 = idx >> 6, bb = idx & 63;
            int i = kc + i0, b = b0 + bb;
            float x;
            if (i < 64)       x = vel[b * 64 + i];
            else if (i == 64) x = Kin[b] * INV_MAXSTEPS;
            else              x = 1.0f;
            sX[i0 * K4_TB + bb] = x;
        }
        __syncthreads();
        #pragma unroll 8
        for (int kk = 0; kk < K4_KC; kk++) {
            float4 pv = *reinterpret_cast<const float4*>(&sP[kk * K4_TT + tx * 4]);
            float4 xa = *reinterpret_cast<const float4*>(&sX[kk * K4_TB + iy * 8]);
            float4 xb = *reinterpret_cast<const float4*>(&sX[kk * K4_TB + iy * 8 + 4]);
            float xv[8] = {xa.x, xa.y, xa.z, xa.w, xb.x, xb.y, xb.z, xb.w};
            float pr[4] = {pv.x, pv.y, pv.z, pv.w};
            #pragma unroll
            for (int r = 0; r < 8; r++)
                #pragma unroll
                for (int s = 0; s < 4; s++)
                    acc[r][s] = fmaf(xv[r], pr[s], acc[r][s]);
        }
    }
    #pragma unroll
    for (int r = 0; r < 8; r++) {
        int b = b0 + iy * 8 + r;
        float a = sA[iy * 8 + r];
        float4 o = make_float4(a * acc[r][0], a * acc[r][1], a * acc[r][2], a * acc[r][3]);
        *reinterpret_cast<float4*>(&out[b * WSZ + t0 + tx * 4]) = o;
    }
}

// ---------------------------------------------------------------------------
extern "C" void kernel_launch(void* const* d_in, const int* in_sizes, int n_in,
                              void* d_out, int out_size) {
    const float* vel = (const float*)d_in[0];
    const float* Kin = (const float*)d_in[1];
    const float* eps = (const float*)d_in[2];
    const float* Wc  = (const float*)d_in[3];
    const float* bc  = (const float*)d_in[4];
    const float* Wa  = (const float*)d_in[5];
    const float* ba  = (const float*)d_in[6];
    const float* Wm  = (const float*)d_in[7];
    const float* bm  = (const float*)d_in[8];
    float* out = (float*)d_out;

    k_init  <<< (NA * WSZ / 4 + 255) / 256, 256 >>> ();
    k_center<<< NA, 256 >>> (Wc, bc);
    k_stats <<< 32, 1024 >>> (vel, Kin, Wa, ba, Wm, bm, out, out_size);
    k_gmax  <<< 512, 256 >>> (eps);
    k_mmat  <<< dim3(4, MM_KSPLIT), 288 >>> (Wc, bc);
    k_conv  <<< dim3(WSZ / 128, K3_DSPLIT), 288 >>> (eps);
    k_out   <<< dim3(WSZ / K4_TT, BATCH / K4_TB), 256 >>> (vel, Kin, out);
}

// round 4
// speedup vs baseline: 1.6026x; 1.1049x over previous
#include <cuda_runtime.h>
#include <math.h>

#define BATCH 1024
#define WSZ   8192
#define DIN   65
#define NA    66
#define IRL   16382
#define MI_N  513
#define INV_MAXSTEPS (1.0f/2799.0f)
#define PI_OVER_8191 (3.14159265358979323846f/8191.0f)

__device__ float        g_mean[BATCH];
__device__ float        g_amps[BATCH];
__device__ unsigned int g_max_u;
__device__ float        g_D[MI_N * NA];   // windowed DCT columns [mi][i], h folded
__device__ float        g_P[NA * WSZ];    // conv result [i][t]

// ---------------------------------------------------------------------------
__global__ void k_init() {
    int idx = blockIdx.x * blockDim.x + threadIdx.x;
    if (idx < (NA * WSZ) / 4)
        reinterpret_cast<float4*>(g_P)[idx] = make_float4(0.f, 0.f, 0.f, 0.f);
    if (idx < MI_N * NA) g_D[idx] = 0.0f;
    if (idx == 0)        g_max_u = 0u;
}

// ---------------------------------------------------------------------------
// Center column mi=512 (m=8191): cos(2*pi*8191*k/16382) = (-1)^k, h=1.
__global__ void k_center(const float* __restrict__ Wc, const float* __restrict__ bc) {
    __shared__ float red[8];
    int i = blockIdx.x;
    const float* row = (i < DIN) ? &Wc[i * WSZ] : bc;
    float s = 0.0f;
    for (int k = threadIdx.x; k < WSZ; k += 256) {
        float gk = (k == 0 || k == WSZ - 1) ? 1.0f : 2.0f;
        float sgn = (k & 1) ? -1.0f : 1.0f;
        s += row[k] * gk * sgn;
    }
    #pragma unroll
    for (int o = 16; o; o >>= 1) s += __shfl_xor_sync(0xffffffffu, s, o);
    if ((threadIdx.x & 31) == 0) red[threadIdx.x >> 5] = s;
    __syncthreads();
    if (threadIdx.x == 0) {
        float t = 0.0f;
        #pragma unroll
        for (int w = 0; w < 8; w++) t += red[w];
        g_D[512 * NA + i] = t * (1.0f / 16382.0f);
    }
}

// ---------------------------------------------------------------------------
__global__ void k_stats(const float* __restrict__ vel, const float* __restrict__ Kin,
                        const float* __restrict__ Wa, const float* __restrict__ ba,
                        const float* __restrict__ Wm, const float* __restrict__ bm,
                        float* __restrict__ out, int out_size) {
    int gw = (blockIdx.x * blockDim.x + threadIdx.x) >> 5;
    int lane = threadIdx.x & 31;
    if (gw >= BATCH) return;
    float sa = 0.0f, sm = 0.0f;
    #pragma unroll
    for (int i = lane; i < 64; i += 32) {
        float x = vel[gw * 64 + i];
        sa += x * Wa[i];
        sm += x * Wm[i];
    }
    if (lane == 0) {
        float xk = Kin[gw] * INV_MAXSTEPS;
        sa += xk * Wa[64];
        sm += xk * Wm[64];
    }
    #pragma unroll
    for (int o = 16; o; o >>= 1) {
        sa += __shfl_down_sync(0xffffffffu, sa, o);
        sm += __shfl_down_sync(0xffffffffu, sm, o);
    }
    if (lane == 0) {
        float m = tanhf(sm + bm[0]);
        float a = 1.0f / (1.0f + expf(-(sa + ba[0])));
        g_mean[gw] = m;
        g_amps[gw] = a;
        if (out_size >= BATCH * WSZ + BATCH)
            out[BATCH * WSZ + gw] = m;
    }
}

// ---------------------------------------------------------------------------
// Global max of mean[b]+eps[b,t], 4 independent accumulators for MLP.
__global__ void k_gmax(const float* __restrict__ eps) {
    const int N4 = (BATCH * WSZ) / 4;
    const float NEG = __int_as_float(0xff800000);
    int stride = gridDim.x * blockDim.x;
    int i0 = blockIdx.x * blockDim.x + threadIdx.x;
    const float4* e4 = reinterpret_cast<const float4*>(eps);
    float a0 = NEG, a1 = NEG, a2 = NEG, a3 = NEG;
    for (int j = i0; j < N4; j += 4 * stride) {
        int j1 = j + stride, j2 = j + 2 * stride, j3 = j + 3 * stride;
        float4 v0 = e4[j];
        float4 v1 = (j1 < N4) ? e4[j1] : make_float4(NEG,NEG,NEG,NEG);
        float4 v2 = (j2 < N4) ? e4[j2] : make_float4(NEG,NEG,NEG,NEG);
        float4 v3 = (j3 < N4) ? e4[j3] : make_float4(NEG,NEG,NEG,NEG);
        float m0 = g_mean[j >> 11];
        float m1 = (j1 < N4) ? g_mean[j1 >> 11] : 0.0f;
        float m2 = (j2 < N4) ? g_mean[j2 >> 11] : 0.0f;
        float m3 = (j3 < N4) ? g_mean[j3 >> 11] : 0.0f;
        a0 = fmaxf(a0, m0 + fmaxf(fmaxf(v0.x, v0.y), fmaxf(v0.z, v0.w)));
        a1 = fmaxf(a1, m1 + fmaxf(fmaxf(v1.x, v1.y), fmaxf(v1.z, v1.w)));
        a2 = fmaxf(a2, m2 + fmaxf(fmaxf(v2.x, v2.y), fmaxf(v2.z, v2.w)));
        a3 = fmaxf(a3, m3 + fmaxf(fmaxf(v3.x, v3.y), fmaxf(v3.z, v3.w)));
    }
    float lm = fmaxf(fmaxf(a0, a1), fmaxf(a2, a3));
    #pragma unroll
    for (int o = 16; o; o >>= 1)
        lm = fmaxf(lm, __shfl_xor_sync(0xffffffffu, lm, o));
    if ((threadIdx.x & 31) == 0) {
        unsigned b = __float_as_uint(lm);
        unsigned enc = (b & 0x80000000u) ? ~b : (b | 0x80000000u);
        atomicMax(&g_max_u, enc);
    }
}

// ---------------------------------------------------------------------------
// Double-folded DCT: using cos(2*pi*(8191-k)m/IRL) = (-1)^m cos(2*pi*k*m/IRL),
// g_D[mi][i] = h/16382 * sum_{k=0..4095} [gW_k +/- gW_{8191-k}](i) * cos(2*pi*k*m/IRL)
// (+ for m even, - for m odd), m = 7679+mi, mi in [0,512).
// Block: 288 thr = 9 warps x (8 i). Thread: 4 m x 8 i. Grid (4 m-tiles, 64 k-chunks of 64).
#define MM_KSPLIT 64
#define MM_SUB 32
__global__ void __launch_bounds__(288) k_mmat(const float* __restrict__ Wc,
                                              const float* __restrict__ bc) {
    __shared__ float sWe[MM_SUB * 76];
    __shared__ float sWo[MM_SUB * 76];
    __shared__ float sC[MM_SUB * 128];
    int tid = threadIdx.x;
    int tx = tid & 31;
    int iy = tid >> 5;
    int mi0 = blockIdx.x * 128;
    int k0  = blockIdx.y * 64;

    int mfill = tid & 127;
    int half  = (tid >> 7) & 1;
    int mmf = 7679 + mi0 + mfill;
    int ph = 0, step = 0;
    if (tid < 256) {
        ph = (int)(((long long)(k0 + half) * (long long)mmf) % IRL);
        step = 2 * mmf; if (step >= IRL) step -= IRL;
    }

    float acc[8][4];
    #pragma unroll
    for (int q = 0; q < 8; q++)
        #pragma unroll
        for (int r = 0; r < 4; r++) acc[q][r] = 0.0f;

    for (int c = 0; c < 64 / MM_SUB; c++) {
        int kc = k0 + c * MM_SUB;
        __syncthreads();
        for (int idx = tid; idx < 72 * MM_SUB; idx += 288) {
            int i = idx >> 5, kk = idx & 31;
            int k = kc + kk, kb = 8191 - k;
            float va = (i < DIN) ? Wc[i * WSZ + k]  : (i == DIN ? bc[k]  : 0.0f);
            float vb = (i < DIN) ? Wc[i * WSZ + kb] : (i == DIN ? bc[kb] : 0.0f);
            float ga = (k == 0) ? 1.0f : 2.0f;
            float gb = (kb == WSZ - 1) ? 1.0f : 2.0f;
            float e = va * ga + vb * gb;
            float o = va * ga - vb * gb;
            sWe[kk * 76 + i] = e;
            sWo[kk * 76 + i] = o;
        }
        if (tid < 256) {
            int p = ph;
            #pragma unroll
            for (int s = 0; s < 16; s++) {
                int p2 = p - ((p >= 8191) ? IRL : 0);
                sC[(half + 2 * s) * 128 + mfill] = __cosf((float)p2 * PI_OVER_8191);
                p += step; if (p >= IRL) p -= IRL;
            }
            ph = p;
        }
        __syncthreads();
        #pragma unroll 8
        for (int kk = 0; kk < MM_SUB; kk++) {
            float4 cv = *reinterpret_cast<const float4*>(&sC[kk * 128 + tx * 4]);
            float4 ea = *reinterpret_cast<const float4*>(&sWe[kk * 76 + iy * 8]);
            float4 eb = *reinterpret_cast<const float4*>(&sWe[kk * 76 + iy * 8 + 4]);
            float4 oa = *reinterpret_cast<const float4*>(&sWo[kk * 76 + iy * 8]);
            float4 ob = *reinterpret_cast<const float4*>(&sWo[kk * 76 + iy * 8 + 4]);
            float ev[8] = {ea.x, ea.y, ea.z, ea.w, eb.x, eb.y, eb.z, eb.w};
            float ov[8] = {oa.x, oa.y, oa.z, oa.w, ob.x, ob.y, ob.z, ob.w};
            // mi = mi0 + tx*4 + r; m = 7679+mi odd when r even -> Wo; else We
            #pragma unroll
            for (int q = 0; q < 8; q++) {
                acc[q][0] = fmaf(ov[q], cv.x, acc[q][0]);
                acc[q][1] = fmaf(ev[q], cv.y, acc[q][1]);
                acc[q][2] = fmaf(ov[q], cv.z, acc[q][2]);
                acc[q][3] = fmaf(ev[q], cv.w, acc[q][3]);
            }
        }
    }

    #pragma unroll
    for (int r = 0; r < 4; r++) {
        int mi = mi0 + tx * 4 + r;          // < 512
        int jh = (mi >= 2) ? (mi - 2) : (1022 - mi);
        float h = 0.5f - 0.5f * cospif((float)(jh + 2) * (1.0f / 512.0f));
        float sc = h * (1.0f / 16382.0f);
        #pragma unroll
        for (int q = 0; q < 8; q++) {
            int i = iy * 8 + q;
            if (i < NA)
                atomicAdd(&g_D[mi * NA + i], acc[q][r] * sc);
        }
    }
}

// ---------------------------------------------------------------------------
// Folded symmetric FIR:
// P[i][t] = D[512][i]*n0[t] + sum_{d=1..510} D[512-d][i]*(n0[t+d]+n0[t-d])
//           + D[1][i]*n0[t-511] + D[0][i]*n0[t-512]
#define K3_DSPLIT 4
__global__ void __launch_bounds__(288) k_conv(const float* __restrict__ eps) {
    __shared__ float sN[1152];
    __shared__ float sM[32 * 76];
    __shared__ float sF[32 * 132];
    int tid = threadIdx.x;
    int tx = tid & 31;
    int iy = tid >> 5;
    int t0 = blockIdx.x * 128;
    int y  = blockIdx.y;

    float mean0 = g_mean[0];
    unsigned enc = g_max_u;
    float gmax = (enc & 0x80000000u) ? __uint_as_float(enc & 0x7fffffffu)
                                     : __uint_as_float(~enc);
    float inv = 1.0f / gmax;
    for (int s = tid; s < 1152; s += 288) {
        int u = t0 - 512 + s;
        sN[s] = (u >= 0 && u < WSZ) ? (mean0 + eps[u]) * inv : 0.0f;
    }
    __syncthreads();

    float acc[8][4];
    #pragma unroll
    for (int q = 0; q < 8; q++)
        #pragma unroll
        for (int s = 0; s < 4; s++) acc[q][s] = 0.0f;

    if (y == 0) {
        #pragma unroll
        for (int q = 0; q < 8; q++) {
            int i = iy * 8 + q;
            if (i < NA) {
                float mC = g_D[512 * NA + i];
                float m1 = g_D[1 * NA + i];
                float m0 = g_D[0 * NA + i];
                #pragma unroll
                for (int s = 0; s < 4; s++) {
                    int x = 512 + tx * 4 + s;
                    acc[q][s] = mC * sN[x] + m1 * sN[x - 511] + m0 * sN[x - 512];
                }
            }
        }
    }

    for (int c = 0; c < 4; c++) {
        int d0 = 1 + 128 * y + 32 * c;
        __syncthreads();
        for (int idx = tid; idx < 32 * 72; idx += 288) {
            int dd = idx / 72, i = idx % 72;
            int mi = 512 - (d0 + dd);
            sM[dd * 76 + i] = (i < NA && mi >= 2) ? g_D[mi * NA + i] : 0.0f;
        }
        for (int idx = tid; idx < 32 * 128; idx += 288) {
            int dd = idx >> 7, tt = idx & 127;
            int d = d0 + dd;
            int x = 512 + tt;
            sF[dd * 132 + tt] = sN[x + d] + sN[x - d];
        }
        __syncthreads();
        #pragma unroll 8
        for (int dd = 0; dd < 32; dd++) {
            float4 fv = *reinterpret_cast<const float4*>(&sF[dd * 132 + tx * 4]);
            float4 ma = *reinterpret_cast<const float4*>(&sM[dd * 76 + iy * 8]);
            float4 mb = *reinterpret_cast<const float4*>(&sM[dd * 76 + iy * 8 + 4]);
            float mv[8] = {ma.x, ma.y, ma.z, ma.w, mb.x, mb.y, mb.z, mb.w};
            #pragma unroll
            for (int q = 0; q < 8; q++) {
                acc[q][0] = fmaf(mv[q], fv.x, acc[q][0]);
                acc[q][1] = fmaf(mv[q], fv.y, acc[q][1]);
                acc[q][2] = fmaf(mv[q], fv.z, acc[q][2]);
                acc[q][3] = fmaf(mv[q], fv.w, acc[q][3]);
            }
        }
    }

    #pragma unroll
    for (int q = 0; q < 8; q++) {
        int i = iy * 8 + q;
        if (i < NA) {
            #pragma unroll
            for (int s = 0; s < 4; s++)
                atomicAdd(&g_P[i * WSZ + t0 + tx * 4 + s], acc[q][s]);
        }
    }
}

// ---------------------------------------------------------------------------
#define K4_TB 64
#define K4_TT 128
#define K4_KC 33
__global__ void __launch_bounds__(256) k_out(const float* __restrict__ vel,
                                             const float* __restrict__ Kin,
                                             float* __restrict__ out) {
    __shared__ float sP[K4_KC * K4_TT];
    __shared__ float sX[K4_KC * K4_TB];
    __shared__ float sA[K4_TB];
    int tid = threadIdx.x;
    int tx = tid & 31;
    int iy = tid >> 5;
    int t0 = blockIdx.x * K4_TT;
    int b0 = blockIdx.y * K4_TB;
    if (tid < K4_TB) sA[tid] = g_amps[b0 + tid];

    float acc[8][4];
    #pragma unroll
    for (int r = 0; r < 8; r++)
        #pragma unroll
        for (int s = 0; s < 4; s++) acc[r][s] = 0.0f;

    for (int kc = 0; kc < NA; kc += K4_KC) {
        __syncthreads();
        for (int idx = tid; idx < K4_KC * K4_TT; idx += 256) {
            int i = idx >> 7, tt = idx & 127;
            sP[idx] = g_P[(kc + i) * WSZ + t0 + tt];
        }
        for (int idx = tid; idx < K4_KC * K4_TB; idx += 256) {
            int i0 = idx >> 6, bb = idx & 63;
            int i = kc + i0, b = b0 + bb;
            float x;
            if (i < 64)       x = vel[b * 64 + i];
            else if (i == 64) x = Kin[b] * INV_MAXSTEPS;
            else              x = 1.0f;
            sX[i0 * K4_TB + bb] = x;
        }
        __syncthreads();
        #pragma unroll 8
        for (int kk = 0; kk < K4_KC; kk++) {
            float4 pv = *reinterpret_cast<const float4*>(&sP[kk * K4_TT + tx * 4]);
            float4 xa = *reinterpret_cast<const float4*>(&sX[kk * K4_TB + iy * 8]);
            float4 xb = *reinterpret_cast<const float4*>(&sX[kk * K4_TB + iy * 8 + 4]);
            float xv[8] = {xa.x, xa.y, xa.z, xa.w, xb.x, xb.y, xb.z, xb.w};
            #pragma unroll
            for (int r = 0; r < 8; r++) {
                acc[r][0] = fmaf(xv[r], pv.x, acc[r][0]);
                acc[r][1] = fmaf(xv[r], pv.y, acc[r][1]);
                acc[r][2] = fmaf(xv[r], pv.z, acc[r][2]);
                acc[r][3] = fmaf(xv[r], pv.w, acc[r][3]);
            }
        }
    }
    #pragma unroll
    for (int r = 0; r < 8; r++) {
        int b = b0 + iy * 8 + r;
        float a = sA[iy * 8 + r];
        float4 o = make_float4(a * acc[r][0], a * acc[r][1], a * acc[r][2], a * acc[r][3]);
        *reinterpret_cast<float4*>(&out[b * WSZ + t0 + tx * 4]) = o;
    }
}

// ---------------------------------------------------------------------------
// Side streams + events for fork/join inside graph capture (created once at
// load time; no device memory involved).
static cudaStream_t s_aux1, s_aux2;
static cudaEvent_t  ev_root, ev_j1, ev_j2;
namespace {
struct StreamBoot {
    StreamBoot() {
        cudaStreamCreateWithFlags(&s_aux1, cudaStreamNonBlocking);
        cudaStreamCreateWithFlags(&s_aux2, cudaStreamNonBlocking);
        cudaEventCreateWithFlags(&ev_root, cudaEventDisableTiming);
        cudaEventCreateWithFlags(&ev_j1,   cudaEventDisableTiming);
        cudaEventCreateWithFlags(&ev_j2,   cudaEventDisableTiming);
    }
};
static StreamBoot g_stream_boot;
}

extern "C" void kernel_launch(void* const* d_in, const int* in_sizes, int n_in,
                              void* d_out, int out_size) {
    const float* vel = (const float*)d_in[0];
    const float* Kin = (const float*)d_in[1];
    const float* eps = (const float*)d_in[2];
    const float* Wc  = (const float*)d_in[3];
    const float* bc  = (const float*)d_in[4];
    const float* Wa  = (const float*)d_in[5];
    const float* ba  = (const float*)d_in[6];
    const float* Wm  = (const float*)d_in[7];
    const float* bm  = (const float*)d_in[8];
    float* out = (float*)d_out;

    // main stream: init -> mmat -> (join) -> conv -> out
    k_init  <<< (NA * WSZ / 4 + 255) / 256, 256 >>> ();
    cudaEventRecord(ev_root, 0);
    cudaStreamWaitEvent(s_aux1, ev_root, 0);
    cudaStreamWaitEvent(s_aux2, ev_root, 0);

    // aux1: stats -> gmax
    k_stats <<< 32, 1024, 0, s_aux1 >>> (vel, Kin, Wa, ba, Wm, bm, out, out_size);
    k_gmax  <<< 1024, 256, 0, s_aux1 >>> (eps);
    cudaEventRecord(ev_j1, s_aux1);

    // aux2: center column
    k_center<<< NA, 256, 0, s_aux2 >>> (Wc, bc);
    cudaEventRecord(ev_j2, s_aux2);

    k_mmat  <<< dim3(4, MM_KSPLIT), 288 >>> (Wc, bc);
    cudaStreamWaitEvent(0, ev_j1, 0);
    cudaStreamWaitEvent(0, ev_j2, 0);
    k_conv  <<< dim3(WSZ / 128, K3_DSPLIT), 288 >>> (eps);
    k_out   <<< dim3(WSZ / K4_TT, BATCH / K4_TB), 256 >>> (vel, Kin, out);
}

// round 5
// speedup vs baseline: 1.7247x; 1.0762x over previous
#include <cuda_runtime.h>
#include <math.h>

#define BATCH 1024
#define WSZ   8192
#define DIN   65
#define NA    66
#define IRL   16382
#define MI_N  513
#define INV_MAXSTEPS (1.0f/2799.0f)
#define PI_OVER_8191 (3.14159265358979323846f/8191.0f)

__device__ float        g_mean[BATCH];
__device__ float        g_amps[BATCH];
__device__ unsigned int g_max_u;
__device__ float        g_D[MI_N * NA];   // windowed DCT columns [mi][i], h folded
__device__ float        g_P[NA * WSZ];    // conv result [i][t]

__device__ __forceinline__ unsigned f2tf32(float f) {
    unsigned u;
    asm("cvt.rna.tf32.f32 %0, %1;" : "=r"(u) : "f"(f));
    return u;
}

// ---------------------------------------------------------------------------
__global__ void k_init() {
    int idx = blockIdx.x * blockDim.x + threadIdx.x;
    if (idx < (NA * WSZ) / 4)
        reinterpret_cast<float4*>(g_P)[idx] = make_float4(0.f, 0.f, 0.f, 0.f);
    if (idx < MI_N * NA) g_D[idx] = 0.0f;
    if (idx == 0)        g_max_u = 0u;
}

// ---------------------------------------------------------------------------
// Center column mi=512 (m=8191): cos = (-1)^k, h=1. Split-k x8 + atomicAdd.
__global__ void k_center(const float* __restrict__ Wc, const float* __restrict__ bc) {
    __shared__ float red[8];
    int i = blockIdx.x;                  // 0..65
    int kc = blockIdx.y * 1024;          // 8 chunks of 1024
    const float* row = (i < DIN) ? &Wc[i * WSZ] : bc;
    float s = 0.0f;
    for (int k = kc + threadIdx.x; k < kc + 1024; k += 256) {
        float gk = (k == 0 || k == WSZ - 1) ? 1.0f : 2.0f;
        float sgn = (k & 1) ? -1.0f : 1.0f;
        s += row[k] * gk * sgn;
    }
    #pragma unroll
    for (int o = 16; o; o >>= 1) s += __shfl_xor_sync(0xffffffffu, s, o);
    if ((threadIdx.x & 31) == 0) red[threadIdx.x >> 5] = s;
    __syncthreads();
    if (threadIdx.x == 0) {
        float t = 0.0f;
        #pragma unroll
        for (int w = 0; w < 8; w++) t += red[w];
        atomicAdd(&g_D[512 * NA + i], t * (1.0f / 16382.0f));
    }
}

// ---------------------------------------------------------------------------
__global__ void k_stats(const float* __restrict__ vel, const float* __restrict__ Kin,
                        const float* __restrict__ Wa, const float* __restrict__ ba,
                        const float* __restrict__ Wm, const float* __restrict__ bm,
                        float* __restrict__ out, int out_size) {
    int gw = (blockIdx.x * blockDim.x + threadIdx.x) >> 5;
    int lane = threadIdx.x & 31;
    if (gw >= BATCH) return;
    float sa = 0.0f, sm = 0.0f;
    #pragma unroll
    for (int i = lane; i < 64; i += 32) {
        float x = vel[gw * 64 + i];
        sa += x * Wa[i];
        sm += x * Wm[i];
    }
    if (lane == 0) {
        float xk = Kin[gw] * INV_MAXSTEPS;
        sa += xk * Wa[64];
        sm += xk * Wm[64];
    }
    #pragma unroll
    for (int o = 16; o; o >>= 1) {
        sa += __shfl_down_sync(0xffffffffu, sa, o);
        sm += __shfl_down_sync(0xffffffffu, sm, o);
    }
    if (lane == 0) {
        float m = tanhf(sm + bm[0]);
        float a = 1.0f / (1.0f + expf(-(sa + ba[0])));
        g_mean[gw] = m;
        g_amps[gw] = a;
        if (out_size >= BATCH * WSZ + BATCH)
            out[BATCH * WSZ + gw] = m;
    }
}

// ---------------------------------------------------------------------------
__global__ void k_gmax(const float* __restrict__ eps) {
    const int N4 = (BATCH * WSZ) / 4;
    const float NEG = __int_as_float(0xff800000);
    int stride = gridDim.x * blockDim.x;
    int i0 = blockIdx.x * blockDim.x + threadIdx.x;
    const float4* e4 = reinterpret_cast<const float4*>(eps);
    float a0 = NEG, a1 = NEG, a2 = NEG, a3 = NEG;
    for (int j = i0; j < N4; j += 4 * stride) {
        int j1 = j + stride, j2 = j + 2 * stride, j3 = j + 3 * stride;
        float4 v0 = e4[j];
        float4 v1 = (j1 < N4) ? e4[j1] : make_float4(NEG,NEG,NEG,NEG);
        float4 v2 = (j2 < N4) ? e4[j2] : make_float4(NEG,NEG,NEG,NEG);
        float4 v3 = (j3 < N4) ? e4[j3] : make_float4(NEG,NEG,NEG,NEG);
        float m0 = g_mean[j >> 11];
        float m1 = (j1 < N4) ? g_mean[j1 >> 11] : 0.0f;
        float m2 = (j2 < N4) ? g_mean[j2 >> 11] : 0.0f;
        float m3 = (j3 < N4) ? g_mean[j3 >> 11] : 0.0f;
        a0 = fmaxf(a0, m0 + fmaxf(fmaxf(v0.x, v0.y), fmaxf(v0.z, v0.w)));
        a1 = fmaxf(a1, m1 + fmaxf(fmaxf(v1.x, v1.y), fmaxf(v1.z, v1.w)));
        a2 = fmaxf(a2, m2 + fmaxf(fmaxf(v2.x, v2.y), fmaxf(v2.z, v2.w)));
        a3 = fmaxf(a3, m3 + fmaxf(fmaxf(v3.x, v3.y), fmaxf(v3.z, v3.w)));
    }
    float lm = fmaxf(fmaxf(a0, a1), fmaxf(a2, a3));
    #pragma unroll
    for (int o = 16; o; o >>= 1)
        lm = fmaxf(lm, __shfl_xor_sync(0xffffffffu, lm, o));
    if ((threadIdx.x & 31) == 0) {
        unsigned b = __float_as_uint(lm);
        unsigned enc = (b & 0x80000000u) ? ~b : (b | 0x80000000u);
        atomicMax(&g_max_u, enc);
    }
}

// ---------------------------------------------------------------------------
// Double-folded DCT (see R3/R4 comments).
#define MM_KSPLIT 64
#define MM_SUB 32
__global__ void __launch_bounds__(288) k_mmat(const float* __restrict__ Wc,
                                              const float* __restrict__ bc) {
    __shared__ float sWe[MM_SUB * 76];
    __shared__ float sWo[MM_SUB * 76];
    __shared__ float sC[MM_SUB * 128];
    int tid = threadIdx.x;
    int tx = tid & 31;
    int iy = tid >> 5;
    int mi0 = blockIdx.x * 128;
    int k0  = blockIdx.y * 64;

    int mfill = tid & 127;
    int half  = (tid >> 7) & 1;
    int mmf = 7679 + mi0 + mfill;
    int ph = 0, step = 0;
    if (tid < 256) {
        ph = (int)(((long long)(k0 + half) * (long long)mmf) % IRL);
        step = 2 * mmf; if (step >= IRL) step -= IRL;
    }

    float acc[8][4];
    #pragma unroll
    for (int q = 0; q < 8; q++)
        #pragma unroll
        for (int r = 0; r < 4; r++) acc[q][r] = 0.0f;

    for (int c = 0; c < 64 / MM_SUB; c++) {
        int kc = k0 + c * MM_SUB;
        __syncthreads();
        for (int idx = tid; idx < 72 * MM_SUB; idx += 288) {
            int i = idx >> 5, kk = idx & 31;
            int k = kc + kk, kb = 8191 - k;
            float va = (i < DIN) ? Wc[i * WSZ + k]  : (i == DIN ? bc[k]  : 0.0f);
            float vb = (i < DIN) ? Wc[i * WSZ + kb] : (i == DIN ? bc[kb] : 0.0f);
            float ga = (k == 0) ? 1.0f : 2.0f;
            float gb = (kb == WSZ - 1) ? 1.0f : 2.0f;
            sWe[kk * 76 + i] = va * ga + vb * gb;
            sWo[kk * 76 + i] = va * ga - vb * gb;
        }
        if (tid < 256) {
            int p = ph;
            #pragma unroll
            for (int s = 0; s < 16; s++) {
                int p2 = p - ((p >= 8191) ? IRL : 0);
                sC[(half + 2 * s) * 128 + mfill] = __cosf((float)p2 * PI_OVER_8191);
                p += step; if (p >= IRL) p -= IRL;
            }
            ph = p;
        }
        __syncthreads();
        #pragma unroll 8
        for (int kk = 0; kk < MM_SUB; kk++) {
            float4 cv = *reinterpret_cast<const float4*>(&sC[kk * 128 + tx * 4]);
            float4 ea = *reinterpret_cast<const float4*>(&sWe[kk * 76 + iy * 8]);
            float4 eb = *reinterpret_cast<const float4*>(&sWe[kk * 76 + iy * 8 + 4]);
            float4 oa = *reinterpret_cast<const float4*>(&sWo[kk * 76 + iy * 8]);
            float4 ob = *reinterpret_cast<const float4*>(&sWo[kk * 76 + iy * 8 + 4]);
            float ev[8] = {ea.x, ea.y, ea.z, ea.w, eb.x, eb.y, eb.z, eb.w};
            float ov[8] = {oa.x, oa.y, oa.z, oa.w, ob.x, ob.y, ob.z, ob.w};
            #pragma unroll
            for (int q = 0; q < 8; q++) {
                acc[q][0] = fmaf(ov[q], cv.x, acc[q][0]);
                acc[q][1] = fmaf(ev[q], cv.y, acc[q][1]);
                acc[q][2] = fmaf(ov[q], cv.z, acc[q][2]);
                acc[q][3] = fmaf(ev[q], cv.w, acc[q][3]);
            }
        }
    }

    #pragma unroll
    for (int r = 0; r < 4; r++) {
        int mi = mi0 + tx * 4 + r;
        int jh = (mi >= 2) ? (mi - 2) : (1022 - mi);
        float h = 0.5f - 0.5f * cospif((float)(jh + 2) * (1.0f / 512.0f));
        float sc = h * (1.0f / 16382.0f);
        #pragma unroll
        for (int q = 0; q < 8; q++) {
            int i = iy * 8 + q;
            if (i < NA)
                atomicAdd(&g_D[mi * NA + i], acc[q][r] * sc);
        }
    }
}

// ---------------------------------------------------------------------------
// Folded symmetric FIR (see R3 comments).
#define K3_DSPLIT 4
__global__ void __launch_bounds__(288) k_conv(const float* __restrict__ eps) {
    __shared__ float sN[1152];
    __shared__ float sM[32 * 76];
    __shared__ float sF[32 * 132];
    int tid = threadIdx.x;
    int tx = tid & 31;
    int iy = tid >> 5;
    int t0 = blockIdx.x * 128;
    int y  = blockIdx.y;

    float mean0 = g_mean[0];
    unsigned enc = g_max_u;
    float gmax = (enc & 0x80000000u) ? __uint_as_float(enc & 0x7fffffffu)
                                     : __uint_as_float(~enc);
    float inv = 1.0f / gmax;
    for (int s = tid; s < 1152; s += 288) {
        int u = t0 - 512 + s;
        sN[s] = (u >= 0 && u < WSZ) ? (mean0 + eps[u]) * inv : 0.0f;
    }
    __syncthreads();

    float acc[8][4];
    #pragma unroll
    for (int q = 0; q < 8; q++)
        #pragma unroll
        for (int s = 0; s < 4; s++) acc[q][s] = 0.0f;

    if (y == 0) {
        #pragma unroll
        for (int q = 0; q < 8; q++) {
            int i = iy * 8 + q;
            if (i < NA) {
                float mC = g_D[512 * NA + i];
                float m1 = g_D[1 * NA + i];
                float m0 = g_D[0 * NA + i];
                #pragma unroll
                for (int s = 0; s < 4; s++) {
                    int x = 512 + tx * 4 + s;
                    acc[q][s] = mC * sN[x] + m1 * sN[x - 511] + m0 * sN[x - 512];
                }
            }
        }
    }

    for (int c = 0; c < 4; c++) {
        int d0 = 1 + 128 * y + 32 * c;
        __syncthreads();
        for (int idx = tid; idx < 32 * 72; idx += 288) {
            int dd = idx / 72, i = idx % 72;
            int mi = 512 - (d0 + dd);
            sM[dd * 76 + i] = (i < NA && mi >= 2) ? g_D[mi * NA + i] : 0.0f;
        }
        for (int idx = tid; idx < 32 * 128; idx += 288) {
            int dd = idx >> 7, tt = idx & 127;
            int d = d0 + dd;
            int x = 512 + tt;
            sF[dd * 132 + tt] = sN[x + d] + sN[x - d];
        }
        __syncthreads();
        #pragma unroll 8
        for (int dd = 0; dd < 32; dd++) {
            float4 fv = *reinterpret_cast<const float4*>(&sF[dd * 132 + tx * 4]);
            float4 ma = *reinterpret_cast<const float4*>(&sM[dd * 76 + iy * 8]);
            float4 mb = *reinterpret_cast<const float4*>(&sM[dd * 76 + iy * 8 + 4]);
            float mv[8] = {ma.x, ma.y, ma.z, ma.w, mb.x, mb.y, mb.z, mb.w};
            #pragma unroll
            for (int q = 0; q < 8; q++) {
                acc[q][0] = fmaf(mv[q], fv.x, acc[q][0]);
                acc[q][1] = fmaf(mv[q], fv.y, acc[q][1]);
                acc[q][2] = fmaf(mv[q], fv.z, acc[q][2]);
                acc[q][3] = fmaf(mv[q], fv.w, acc[q][3]);
            }
        }
    }

    #pragma unroll
    for (int q = 0; q < 8; q++) {
        int i = iy * 8 + q;
        if (i < NA) {
            #pragma unroll
            for (int s = 0; s < 4; s++)
                atomicAdd(&g_P[i * WSZ + t0 + tx * 4 + s], acc[q][s]);
        }
    }
}

// ---------------------------------------------------------------------------
// k_out via tf32 mma.sync.m16n8k8: out[b][t] = amps[b]*sum_i X[b][i]*P[i][t]
// Block tile 64b x 128t, K=72 (padded) resident. 8 warps = 2(b) x 4(t).
#define KO_BT 64
#define KO_TT 128
#define KO_K  72
#define PST 136      // sP row stride (bank-conflict-free for B frags)
#define XST 76       // sX row stride (bank-conflict-free for A frags)
#define KO_SMEM ((KO_K * PST + KO_BT * XST) * 4 + KO_BT * 4)

extern __shared__ unsigned ko_smem[];
__global__ void __launch_bounds__(256) k_out_tc(const float* __restrict__ vel,
                                                const float* __restrict__ Kin,
                                                float* __restrict__ out) {
    unsigned* sP = ko_smem;                    // [KO_K][PST]
    unsigned* sX = ko_smem + KO_K * PST;       // [KO_BT][XST]
    float*    sA = (float*)(sX + KO_BT * XST); // [KO_BT]
    int tid = threadIdx.x, lane = tid & 31, w = tid >> 5;
    int t0 = blockIdx.x * KO_TT, b0 = blockIdx.y * KO_BT;

    for (int idx = tid; idx < KO_K * KO_TT; idx += 256) {
        int i = idx >> 7, tt = idx & 127;
        float v = (i < NA) ? g_P[i * WSZ + t0 + tt] : 0.0f;
        sP[i * PST + tt] = f2tf32(v);
    }
    for (int idx = tid; idx < KO_BT * KO_K; idx += 256) {
        int bb = idx / KO_K, i = idx % KO_K;
        int b = b0 + bb;
        float x;
        if (i < 64)       x = vel[b * 64 + i];
        else if (i == 64) x = Kin[b] * INV_MAXSTEPS;
        else if (i == 65) x = 1.0f;
        else              x = 0.0f;
        sX[bb * XST + i] = f2tf32(x);
    }
    if (tid < KO_BT) sA[tid] = g_amps[b0 + tid];
    __syncthreads();

    int wb = w & 1, wt = w >> 1;
    int r = lane >> 2, cq = lane & 3;
    float c[2][4][4];
    #pragma unroll
    for (int mf = 0; mf < 2; mf++)
        #pragma unroll
        for (int nf = 0; nf < 4; nf++)
            #pragma unroll
            for (int q = 0; q < 4; q++) c[mf][nf][q] = 0.0f;

    #pragma unroll
    for (int s = 0; s < KO_K / 8; s++) {
        int k0 = s * 8;
        unsigned a[2][4];
        #pragma unroll
        for (int mf = 0; mf < 2; mf++) {
            int rb = wb * 32 + mf * 16 + r;
            a[mf][0] = sX[rb * XST + k0 + cq];
            a[mf][1] = sX[(rb + 8) * XST + k0 + cq];
            a[mf][2] = sX[rb * XST + k0 + cq + 4];
            a[mf][3] = sX[(rb + 8) * XST + k0 + cq + 4];
        }
        unsigned bf[4][2];
        #pragma unroll
        for (int nf = 0; nf < 4; nf++) {
            int ct = wt * 32 + nf * 8 + r;
            bf[nf][0] = sP[(k0 + cq) * PST + ct];
            bf[nf][1] = sP[(k0 + cq + 4) * PST + ct];
        }
        #pragma unroll
        for (int mf = 0; mf < 2; mf++)
            #pragma unroll
            for (int nf = 0; nf < 4; nf++) {
                asm volatile(
                    "mma.sync.aligned.m16n8k8.row.col.f32.tf32.tf32.f32 "
                    "{%0,%1,%2,%3}, {%4,%5,%6,%7}, {%8,%9}, {%0,%1,%2,%3};"
                    : "+f"(c[mf][nf][0]), "+f"(c[mf][nf][1]),
                      "+f"(c[mf][nf][2]), "+f"(c[mf][nf][3])
                    : "r"(a[mf][0]), "r"(a[mf][1]), "r"(a[mf][2]), "r"(a[mf][3]),
                      "r"(bf[nf][0]), "r"(bf[nf][1]));
            }
    }

    #pragma unroll
    for (int mf = 0; mf < 2; mf++) {
        int rbl = wb * 32 + mf * 16 + r;
        float a1 = sA[rbl], a2 = sA[rbl + 8];
        int rb = b0 + rbl;
        #pragma unroll
        for (int nf = 0; nf < 4; nf++) {
            int ct = t0 + wt * 32 + nf * 8 + 2 * cq;
            float2 o1 = make_float2(a1 * c[mf][nf][0], a1 * c[mf][nf][1]);
            float2 o2 = make_float2(a2 * c[mf][nf][2], a2 * c[mf][nf][3]);
            *reinterpret_cast<float2*>(&out[rb * WSZ + ct])       = o1;
            *reinterpret_cast<float2*>(&out[(rb + 8) * WSZ + ct]) = o2;
        }
    }
}

// ---------------------------------------------------------------------------
static cudaStream_t s_aux1, s_aux2;
static cudaEvent_t  ev_root, ev_j1, ev_j2;
namespace {
struct StreamBoot {
    StreamBoot() {
        cudaStreamCreateWithFlags(&s_aux1, cudaStreamNonBlocking);
        cudaStreamCreateWithFlags(&s_aux2, cudaStreamNonBlocking);
        cudaEventCreateWithFlags(&ev_root, cudaEventDisableTiming);
        cudaEventCreateWithFlags(&ev_j1,   cudaEventDisableTiming);
        cudaEventCreateWithFlags(&ev_j2,   cudaEventDisableTiming);
    }
};
static StreamBoot g_stream_boot;
}

extern "C" void kernel_launch(void* const* d_in, const int* in_sizes, int n_in,
                              void* d_out, int out_size) {
    const float* vel = (const float*)d_in[0];
    const float* Kin = (const float*)d_in[1];
    const float* eps = (const float*)d_in[2];
    const float* Wc  = (const float*)d_in[3];
    const float* bc  = (const float*)d_in[4];
    const float* Wa  = (const float*)d_in[5];
    const float* ba  = (const float*)d_in[6];
    const float* Wm  = (const float*)d_in[7];
    const float* bm  = (const float*)d_in[8];
    float* out = (float*)d_out;

    cudaFuncSetAttribute(k_out_tc, cudaFuncAttributeMaxDynamicSharedMemorySize, KO_SMEM);

    k_init  <<< (NA * WSZ / 4 + 255) / 256, 256 >>> ();
    cudaEventRecord(ev_root, 0);
    cudaStreamWaitEvent(s_aux1, ev_root, 0);
    cudaStreamWaitEvent(s_aux2, ev_root, 0);

    k_stats <<< 32, 1024, 0, s_aux1 >>> (vel, Kin, Wa, ba, Wm, bm, out, out_size);
    k_gmax  <<< 1024, 256, 0, s_aux1 >>> (eps);
    cudaEventRecord(ev_j1, s_aux1);

    k_center<<< dim3(NA, 8), 256, 0, s_aux2 >>> (Wc, bc);
    cudaEventRecord(ev_j2, s_aux2);

    k_mmat  <<< dim3(4, MM_KSPLIT), 288 >>> (Wc, bc);
    cudaStreamWaitEvent(0, ev_j1, 0);
    cudaStreamWaitEvent(0, ev_j2, 0);
    k_conv  <<< dim3(WSZ / 128, K3_DSPLIT), 288 >>> (eps);
    k_out_tc<<< dim3(WSZ / KO_TT, BATCH / KO_BT), 256, KO_SMEM >>> (vel, Kin, out);
}